// round 1
// baseline (speedup 1.0000x reference)
#include <cuda_runtime.h>
#include <math.h>

#define NUM_CLASSES 8192
#define BATCH 256
#define THREADS 256
#define SEESAW_EPS 1e-6f

__device__ float g_rowloss[BATCH];

__global__ __launch_bounds__(THREADS)
void seesaw_row_kernel(const float* __restrict__ logits,
                       const float* __restrict__ targets,
                       const float* __restrict__ s)
{
    const int b   = blockIdx.x;
    const int tid = threadIdx.x;

    const float4* lg4 = reinterpret_cast<const float4*>(logits + (size_t)b * NUM_CLASSES);
    const float4* tg4 = reinterpret_cast<const float4*>(targets + (size_t)b * NUM_CLASSES);

    __shared__ float s_warpmax[THREADS / 32];
    __shared__ float s_rowmax;
    __shared__ int   s_y;      // label index for this row
    __shared__ float s_ty;     // target value at label (1.0 for one-hot)
    __shared__ float s_warpdot[THREADS / 32];

    if (tid == 0) { s_y = 0; s_ty = 0.0f; }
    __syncthreads();

    // ---- Pass 1: row max of logits + find the (single) nonzero target ----
    float m = -INFINITY;
    #pragma unroll 4
    for (int i = tid; i < NUM_CLASSES / 4; i += THREADS) {
        float4 v = lg4[i];
        m = fmaxf(m, fmaxf(fmaxf(v.x, v.y), fmaxf(v.z, v.w)));
        float4 t = tg4[i];
        // exactly one nonzero per row (one-hot) -> plain writes are race-free
        if (t.x != 0.0f) { s_y = 4 * i + 0; s_ty = t.x; }
        if (t.y != 0.0f) { s_y = 4 * i + 1; s_ty = t.y; }
        if (t.z != 0.0f) { s_y = 4 * i + 2; s_ty = t.z; }
        if (t.w != 0.0f) { s_y = 4 * i + 3; s_ty = t.w; }
    }
    #pragma unroll
    for (int o = 16; o > 0; o >>= 1)
        m = fmaxf(m, __shfl_xor_sync(0xFFFFFFFFu, m, o));
    if ((tid & 31) == 0) s_warpmax[tid >> 5] = m;
    __syncthreads();
    if (tid == 0) {
        float mm = s_warpmax[0];
        #pragma unroll
        for (int w = 1; w < THREADS / 32; w++) mm = fmaxf(mm, s_warpmax[w]);
        s_rowmax = mm;
    }
    __syncthreads();

    const float rowmax = s_rowmax;
    const int   y      = s_y;
    const float4* sr4  = reinterpret_cast<const float4*>(s + (size_t)y * NUM_CLASSES);

    // ---- Pass 2: dot = sum_j (1 - t[b,j]) * s[y,j] * exp(logit[b,j] - rowmax) ----
    float dot = 0.0f;
    #pragma unroll 4
    for (int i = tid; i < NUM_CLASSES / 4; i += THREADS) {
        float4 v  = lg4[i];   // L1/L2 hit (read in pass 1 by this block)
        float4 t  = tg4[i];   // L1/L2 hit
        float4 sv = sr4[i];   // fresh DRAM/L2
        dot += (1.0f - t.x) * sv.x * expf(v.x - rowmax);
        dot += (1.0f - t.y) * sv.y * expf(v.y - rowmax);
        dot += (1.0f - t.z) * sv.z * expf(v.z - rowmax);
        dot += (1.0f - t.w) * sv.w * expf(v.w - rowmax);
    }
    #pragma unroll
    for (int o = 16; o > 0; o >>= 1)
        dot += __shfl_xor_sync(0xFFFFFFFFu, dot, o);
    if ((tid & 31) == 0) s_warpdot[tid >> 5] = dot;
    __syncthreads();

    if (tid == 0) {
        float total = 0.0f;
        #pragma unroll
        for (int w = 0; w < THREADS / 32; w++) total += s_warpdot[w];
        const float expl_y = expf(logits[(size_t)b * NUM_CLASSES + y] - rowmax);
        const float denom  = total + expl_y;
        const float sigma  = expl_y / (denom + SEESAW_EPS);
        g_rowloss[b] = -s_ty * logf(sigma + SEESAW_EPS);
    }
}

__global__ __launch_bounds__(BATCH)
void seesaw_finalize_kernel(float* __restrict__ out)
{
    __shared__ float sh[BATCH];
    sh[threadIdx.x] = g_rowloss[threadIdx.x];
    __syncthreads();
    #pragma unroll
    for (int o = BATCH / 2; o > 0; o >>= 1) {
        if (threadIdx.x < o) sh[threadIdx.x] += sh[threadIdx.x + o];
        __syncthreads();
    }
    if (threadIdx.x == 0) out[0] = sh[0] / (float)BATCH;
}

extern "C" void kernel_launch(void* const* d_in, const int* in_sizes, int n_in,
                              void* d_out, int out_size)
{
    const float* logits  = (const float*)d_in[0];
    const float* targets = (const float*)d_in[1];
    const float* s       = (const float*)d_in[2];
    float* out = (float*)d_out;

    seesaw_row_kernel<<<BATCH, THREADS>>>(logits, targets, s);
    seesaw_finalize_kernel<<<1, BATCH>>>(out);
}

// round 2
// speedup vs baseline: 1.0190x; 1.0190x over previous
#include <cuda_runtime.h>
#include <math.h>

#define NUM_CLASSES 8192
#define BATCH 256
#define THREADS 256
#define SEESAW_EPS 1e-6f

__device__ float g_rowloss[BATCH];
__device__ unsigned int g_ticket;   // zero-initialized; reset by the last block each run

__global__ __launch_bounds__(THREADS)
void seesaw_fused_kernel(const float* __restrict__ logits,
                         const float* __restrict__ targets,
                         const float* __restrict__ s,
                         float* __restrict__ out)
{
    const int b   = blockIdx.x;
    const int tid = threadIdx.x;

    const float4* lg4 = reinterpret_cast<const float4*>(logits  + (size_t)b * NUM_CLASSES);
    const float4* tg4 = reinterpret_cast<const float4*>(targets + (size_t)b * NUM_CLASSES);

    __shared__ int   s_y;                      // label index for this row
    __shared__ float s_warpdot[THREADS / 32];
    __shared__ int   s_last;

    if (tid == 0) s_y = 0;
    __syncthreads();

    // ---- Pass A: scan one-hot targets row to find label index y ----
    #pragma unroll 4
    for (int i = tid; i < NUM_CLASSES / 4; i += THREADS) {
        float4 t = tg4[i];
        // exactly one nonzero per row -> unsynchronized write is race-free
        if (t.x != 0.0f) s_y = 4 * i + 0;
        if (t.y != 0.0f) s_y = 4 * i + 1;
        if (t.z != 0.0f) s_y = 4 * i + 2;
        if (t.w != 0.0f) s_y = 4 * i + 3;
    }
    __syncthreads();

    const int y = s_y;
    const float4* sr4 = reinterpret_cast<const float4*>(s + (size_t)y * NUM_CLASSES);

    // ---- Pass B: denom = sum_j s[y,j] * exp(logits[b,j])  (no shift, no mask:
    //      s[y,y]==1 makes the diagonal term exactly the +expl_y of the reference) ----
    float dot = 0.0f;
    #pragma unroll 4
    for (int i = tid; i < NUM_CLASSES / 4; i += THREADS) {
        float4 v  = lg4[i];
        float4 sv = sr4[i];
        dot += sv.x * __expf(v.x);
        dot += sv.y * __expf(v.y);
        dot += sv.z * __expf(v.z);
        dot += sv.w * __expf(v.w);
    }
    #pragma unroll
    for (int o = 16; o > 0; o >>= 1)
        dot += __shfl_xor_sync(0xFFFFFFFFu, dot, o);
    if ((tid & 31) == 0) s_warpdot[tid >> 5] = dot;
    __syncthreads();

    if (tid == 0) {
        float denom = 0.0f;
        #pragma unroll
        for (int w = 0; w < THREADS / 32; w++) denom += s_warpdot[w];
        const float expl_y = __expf(logits[(size_t)b * NUM_CLASSES + y]);
        const float sigma  = expl_y / (denom + SEESAW_EPS);
        g_rowloss[b] = -logf(sigma + SEESAW_EPS);

        __threadfence();
        unsigned int prev = atomicAdd(&g_ticket, 1u);
        s_last = (prev == (unsigned int)(BATCH - 1)) ? 1 : 0;
    }
    __syncthreads();

    // ---- Last block to finish reduces all row losses and writes the mean ----
    if (s_last) {
        __shared__ float sh[BATCH];
        volatile float* rl = g_rowloss;
        sh[tid] = rl[tid];
        __syncthreads();
        #pragma unroll
        for (int o = BATCH / 2; o > 0; o >>= 1) {
            if (tid < o) sh[tid] += sh[tid + o];
            __syncthreads();
        }
        if (tid == 0) {
            out[0] = sh[0] / (float)BATCH;
            g_ticket = 0u;   // reset for the next graph replay (deterministic)
        }
    }
}

extern "C" void kernel_launch(void* const* d_in, const int* in_sizes, int n_in,
                              void* d_out, int out_size)
{
    const float* logits  = (const float*)d_in[0];
    const float* targets = (const float*)d_in[1];
    const float* s       = (const float*)d_in[2];
    float* out = (float*)d_out;

    seesaw_fused_kernel<<<BATCH, THREADS>>>(logits, targets, s, out);
}

// round 3
// speedup vs baseline: 1.0805x; 1.0604x over previous
#include <cuda_runtime.h>
#include <math.h>

#define NUM_CLASSES 8192
#define BATCH 256
#define THREADS 512
#define VPT 4                    // float4 chunks per thread per array (16 floats)
#define SEESAW_EPS 1e-6f

__device__ float g_rowloss[BATCH];
__device__ unsigned int g_ticket;   // zero-init; reset by the last block each run

__global__ __launch_bounds__(THREADS)
void seesaw_fused_kernel(const float* __restrict__ logits,
                         const float* __restrict__ targets,
                         const float* __restrict__ s,
                         float* __restrict__ out)
{
    const int b   = blockIdx.x;
    const int tid = threadIdx.x;

    const float4* lg4 = reinterpret_cast<const float4*>(logits  + (size_t)b * NUM_CLASSES);
    const float4* tg4 = reinterpret_cast<const float4*>(targets + (size_t)b * NUM_CLASSES);

    __shared__ int   s_y;
    __shared__ float s_warpdot[THREADS / 32];
    __shared__ int   s_last;

    if (tid == 0) s_y = 0;
    __syncthreads();

    // ---- Phase 1: issue ALL targets+logits loads up front (8 float4 in flight),
    //      exp() into registers, scan one-hot targets for label index ----
    float4 t[VPT], v[VPT];
    #pragma unroll
    for (int k = 0; k < VPT; k++) t[k] = tg4[tid + k * THREADS];
    #pragma unroll
    for (int k = 0; k < VPT; k++) v[k] = lg4[tid + k * THREADS];

    float e[4 * VPT];
    #pragma unroll
    for (int k = 0; k < VPT; k++) {
        e[4 * k + 0] = __expf(v[k].x);
        e[4 * k + 1] = __expf(v[k].y);
        e[4 * k + 2] = __expf(v[k].z);
        e[4 * k + 3] = __expf(v[k].w);
    }
    #pragma unroll
    for (int k = 0; k < VPT; k++) {
        const int base = 4 * (tid + k * THREADS);
        // exactly one nonzero per row (one-hot) -> unsynchronized write is race-free
        if (t[k].x != 0.0f) s_y = base + 0;
        if (t[k].y != 0.0f) s_y = base + 1;
        if (t[k].z != 0.0f) s_y = base + 2;
        if (t[k].w != 0.0f) s_y = base + 3;
    }
    __syncthreads();

    const int y = s_y;
    const float4* sr4 = reinterpret_cast<const float4*>(s + (size_t)y * NUM_CLASSES);

    // ---- Phase 2: gather s[y,:], dot with register-resident expl.
    //      s[y,y]==1 makes the diagonal term exactly the +expl_y of the reference,
    //      and the (1-t) mask is redundant for the one-hot row (term cancels). ----
    float4 sv[VPT];
    #pragma unroll
    for (int k = 0; k < VPT; k++) sv[k] = sr4[tid + k * THREADS];

    float dot = 0.0f;
    #pragma unroll
    for (int k = 0; k < VPT; k++) {
        dot += sv[k].x * e[4 * k + 0];
        dot += sv[k].y * e[4 * k + 1];
        dot += sv[k].z * e[4 * k + 2];
        dot += sv[k].w * e[4 * k + 3];
    }
    #pragma unroll
    for (int o = 16; o > 0; o >>= 1)
        dot += __shfl_xor_sync(0xFFFFFFFFu, dot, o);
    if ((tid & 31) == 0) s_warpdot[tid >> 5] = dot;
    __syncthreads();

    if (tid == 0) {
        float denom = 0.0f;
        #pragma unroll
        for (int w = 0; w < THREADS / 32; w++) denom += s_warpdot[w];
        const float expl_y = __expf(logits[(size_t)b * NUM_CLASSES + y]);
        const float sigma  = expl_y / (denom + SEESAW_EPS);
        g_rowloss[b] = -logf(sigma + SEESAW_EPS);

        __threadfence();
        unsigned int prev = atomicAdd(&g_ticket, 1u);
        s_last = (prev == (unsigned int)(BATCH - 1)) ? 1 : 0;
    }
    __syncthreads();

    // ---- Last-to-finish block reduces row losses, writes mean, resets ticket ----
    if (s_last) {
        __shared__ float sh[BATCH];
        volatile float* rl = g_rowloss;
        if (tid < BATCH) sh[tid] = rl[tid];
        __syncthreads();
        #pragma unroll
        for (int o = BATCH / 2; o > 0; o >>= 1) {
            if (tid < o) sh[tid] += sh[tid + o];
            __syncthreads();
        }
        if (tid == 0) {
            out[0] = sh[0] / (float)BATCH;
            g_ticket = 0u;   // deterministic across graph replays
        }
    }
}

extern "C" void kernel_launch(void* const* d_in, const int* in_sizes, int n_in,
                              void* d_out, int out_size)
{
    const float* logits  = (const float*)d_in[0];
    const float* targets = (const float*)d_in[1];
    const float* s       = (const float*)d_in[2];
    float* out = (float*)d_out;

    seesaw_fused_kernel<<<BATCH, THREADS>>>(logits, targets, s, out);
}